// round 11
// baseline (speedup 1.0000x reference)
#include <cuda_runtime.h>
#include <stdint.h>

#define Mv 128
#define Nv 256
#define Cv 22
#define TILE (Cv*Cv)                  // 484 floats per (i,j) tile
#define JC 32                         // j per chunk
#define NCHUNK (Nv/JC)                // 8 chunks
#define NST 2                         // double buffer
#define STAGE_FLOATS (JC*TILE)        // 15488 floats
#define STAGE_BYTES  (STAGE_FLOATS*4) // 61952 B
#define DSMEM (NST*STAGE_BYTES)       // 123904 B dynamic
#define CHALF 11
#define NB 256

__device__ unsigned g_dselp[(Nv/4) * Mv];   // [j4][m], 4 packed classes/word

__device__ __forceinline__ unsigned smem_u32(const void* p) {
    return (unsigned)__cvta_generic_to_shared(p);
}

__device__ __forceinline__ void wait_parity(unsigned bar, unsigned ph) {
    unsigned done;
    asm volatile("{\n .reg .pred p;\n"
                 " mbarrier.try_wait.parity.acquire.cta.shared::cta.b64 p, [%1], %2;\n"
                 " selp.b32 %0, 1, 0, p;\n}"
                 : "=r"(done) : "r"(bar), "r"(ph) : "memory");
    while (!done) {
        asm volatile("{\n .reg .pred p;\n"
                     " mbarrier.try_wait.parity.acquire.cta.shared::cta.b64 p, [%1], %2, 0x989680;\n"
                     " selp.b32 %0, 1, 0, p;\n}"
                     : "=r"(done) : "r"(bar), "r"(ph) : "memory");
    }
}

// ---------------------------------------------------------------------------
// prep: pack variant -> [j4][m] words; zero vlog (atomicAdd target)
// ---------------------------------------------------------------------------
__global__ void prep_kernel(const int* __restrict__ variant,
                            float* __restrict__ vlog) {
    int tid = blockIdx.x * blockDim.x + threadIdx.x;    // 8192 = 128m x 64 j4
    int m  = tid >> 6;
    int j4 = tid & 63;
    int4 v = ((const int4*)variant)[m * 64 + j4];       // coalesced
    unsigned w = (unsigned)v.x | ((unsigned)v.y << 8) |
                 ((unsigned)v.z << 16) | ((unsigned)v.w << 24);
    g_dselp[j4 * Mv + m] = w;
    if (tid < Mv) vlog[tid] = 0.0f;
}

// ---------------------------------------------------------------------------
// fused: 256 CTAs x 256 threads, JC=32 double-buffered TMA pipeline (8 waits).
// No inter-CTA dependency anywhere -> correct at ANY residency (no deadlock).
// ---------------------------------------------------------------------------
__global__ __launch_bounds__(256, 1) void fused_kernel(
    const int*   __restrict__ variant,
    const float* __restrict__ vmask,
    const float* __restrict__ eij,
    const float* __restrict__ ei,
    const float* __restrict__ mask_vec,
    const float* __restrict__ sigma,
    float* __restrict__ motifs,      // [Mv,Nv,Cv]
    float* __restrict__ logits,      // [Mv,Nv]
    float* __restrict__ vlog)        // [Mv]
{
    extern __shared__ __align__(128) float sE[];        // [NST][STAGE_FLOATS]
    __shared__ __align__(8) unsigned long long mbar[NST];
    __shared__ float smask[32];
    __shared__ float sei[Cv];
    __shared__ float slog[Mv];

    const int i  = blockIdx.x;
    const int t  = threadIdx.x;
    const int m  = t & (Mv - 1);
    const int c0 = (t >> 7) * CHALF;

    if (t < Cv) { smask[t] = mask_vec[t]; sei[t] = ei[i * Cv + t]; }
    if (t == 0) {
        #pragma unroll
        for (int s = 0; s < NST; ++s)
            asm volatile("mbarrier.init.shared.b64 [%0], 1;"
                         :: "r"(smem_u32(&mbar[s])));
    }
    __syncthreads();

    const char* gsrc = (const char*)(eij + (size_t)i * (Nv * TILE));

    // prime both stages
    if (t == 0) {
        #pragma unroll
        for (int k = 0; k < 2; ++k) {
            unsigned bar = smem_u32(&mbar[k]);
            asm volatile("mbarrier.arrive.expect_tx.shared::cta.b64 _, [%0], %1;"
                         :: "r"(bar), "r"((unsigned)STAGE_BYTES));
            asm volatile("cp.async.bulk.shared::cta.global.mbarrier::complete_tx::bytes "
                         "[%0], [%1], %2, [%3];"
                         :: "r"(smem_u32(sE) + k * STAGE_BYTES),
                            "l"(gsrc + (size_t)k * STAGE_BYTES),
                            "r"((unsigned)STAGE_BYTES), "r"(bar) : "memory");
        }
    }

    float acc[CHALF];
    #pragma unroll
    for (int cc = 0; cc < CHALF; ++cc) acc[cc] = 0.0f;

    for (int k = 0; k < NCHUNK; ++k) {
        const int s = k & 1;
        const unsigned ph = (unsigned)(k >> 1) & 1u;

        // 8 coalesced words = 32 class ids, loaded before the wait
        unsigned w8[8];
        #pragma unroll
        for (int q = 0; q < 8; ++q)
            w8[q] = g_dselp[(k * 8 + q) * Mv + m];

        wait_parity(smem_u32(&mbar[s]), ph);

        const float* buf = sE + s * STAGE_FLOATS;
        #pragma unroll
        for (int qp = 0; qp < 4; ++qp) {                // 8 j per quarter-pass
            const unsigned wa = w8[qp * 2], wb = w8[qp * 2 + 1];
            int d8[8];
            #pragma unroll
            for (int b = 0; b < 4; ++b) {
                d8[b]     = (wa >> (8 * b)) & 0xFF;
                d8[4 + b] = (wb >> (8 * b)) & 0xFF;
            }
            float s8[8];
            #pragma unroll
            for (int jj = 0; jj < 8; ++jj) s8[jj] = smask[d8[jj]];

            #pragma unroll
            for (int jl = 0; jl < 8; ++jl) {
                const float* row = buf + (qp * 8 + jl) * TILE + c0 * Cv + d8[jl];
                const float sc = s8[jl];
                #pragma unroll
                for (int cc = 0; cc < CHALF; ++cc)
                    acc[cc] = fmaf(sc, row[cc * Cv], acc[cc]);  // conflict-free LDS
            }
        }

        __syncthreads();   // all done with chunk k -> stage s reusable
        if (t == 0 && k + 2 < NCHUNK) {
            const int kn = k + 2;                       // same stage s, next phase
            unsigned bar = smem_u32(&mbar[s]);
            asm volatile("mbarrier.arrive.expect_tx.shared::cta.b64 _, [%0], %1;"
                         :: "r"(bar), "r"((unsigned)STAGE_BYTES));
            asm volatile("cp.async.bulk.shared::cta.global.mbarrier::complete_tx::bytes "
                         "[%0], [%1], %2, [%3];"
                         :: "r"(smem_u32(sE) + s * STAGE_BYTES),
                            "l"(gsrc + (size_t)kn * STAGE_BYTES),
                            "r"((unsigned)STAGE_BYTES), "r"(bar) : "memory");
        }
    }

    // ---- epilogue: motifs, logits, atomic pooled delta (r9/r10-proven) ----
    const int vmi = variant[m * Nv + i];
    float* mout = motifs + ((size_t)m * Nv + i) * Cv;
    float myl = 0.0f;
    const bool own = (vmi >= c0) && (vmi < c0 + CHALF);
    #pragma unroll
    for (int cc = 0; cc < CHALF; ++cc) {
        const int c = c0 + cc;
        const float v = acc[cc] + sei[c];
        mout[c] = v;
        if (c == vmi) myl = v;
    }
    if (own) slog[m] = myl;
    __syncthreads();

    if (t < Mv) {
        const float lm = slog[t];
        logits[t * Nv + i] = lm;
        const float w = vmask[t * Nv + i] * vmask[i];
        atomicAdd(&vlog[t], (lm - slog[0]) * w * sigma[0]);
    }
}

// ---------------------------------------------------------------------------
// Load-time attribute opt-in (NEVER inside kernel_launch / graph capture).
// ---------------------------------------------------------------------------
static struct _AttrInit {
    _AttrInit() {
        cudaFuncSetAttribute(fused_kernel,
                             cudaFuncAttributeMaxDynamicSharedMemorySize, DSMEM);
    }
} _attr_init;

// ---------------------------------------------------------------------------
extern "C" void kernel_launch(void* const* d_in, const int* in_sizes, int n_in,
                              void* d_out, int out_size) {
    int idx_eij = 2, idx_ei = 3, idx_mask = 4, idx_sigma = 5;
    int big1 = 0, big2 = 1;
    {
        int b1 = -1, b2 = -1;
        for (int q = 0; q < n_in; ++q) {
            int s = in_sizes[q];
            if (s == Nv * Nv * Cv * Cv)      idx_eij = q;
            else if (s == Nv * Cv)           idx_ei = q;
            else if (s == Cv)                idx_mask = q;
            else if (s == 1)                 idx_sigma = q;
            else if (s == Mv * Nv) { if (b1 < 0) b1 = q; else b2 = q; }
        }
        if (b1 >= 0) big1 = b1;
        if (b2 >= 0) big2 = b2;
    }

    const int*   variant = (const int*)d_in[big1];
    const float* vmask   = (const float*)d_in[big2];
    const float* eij     = (const float*)d_in[idx_eij];
    const float* ei      = (const float*)d_in[idx_ei];
    const float* maskv   = (const float*)d_in[idx_mask];
    const float* sigma   = (const float*)d_in[idx_sigma];

    float* out    = (float*)d_out;
    float* motifs = out;                               // [128,256,22]
    float* logits = out + (size_t)Mv * Nv * Cv;        // [128,256]
    float* vlog   = logits + (size_t)Mv * Nv;          // [128,1]

    prep_kernel<<<32, 256>>>(variant, vlog);
    fused_kernel<<<NB, 256, DSMEM>>>(variant, vmask, eij, ei, maskv, sigma,
                                     motifs, logits, vlog);
}

// round 12
// speedup vs baseline: 1.0471x; 1.0471x over previous
#include <cuda_runtime.h>
#include <stdint.h>

#define Mv 128
#define Nv 256
#define Cv 22
#define TILE (Cv*Cv)                  // 484 floats per (i,j) tile
#define JC 8                          // j per chunk
#define NCHUNK (Nv/JC)                // 32 chunks
#define NST 4                         // 4-deep pipeline, sync every 2 chunks
#define STAGE_FLOATS (JC*TILE)        // 3872 floats
#define STAGE_BYTES  (STAGE_FLOATS*4) // 15488 B
#define DSMEM (NST*STAGE_BYTES)       // 61952 B dynamic (same total as r10)
#define CHALF 11
#define NB 256

__device__ unsigned g_dselp[(Nv/4) * Mv];   // [j4][m], 4 packed classes/word

__device__ __forceinline__ unsigned smem_u32(const void* p) {
    return (unsigned)__cvta_generic_to_shared(p);
}

__device__ __forceinline__ void wait_parity(unsigned bar, unsigned ph) {
    unsigned done;
    asm volatile("{\n .reg .pred p;\n"
                 " mbarrier.try_wait.parity.acquire.cta.shared::cta.b64 p, [%1], %2;\n"
                 " selp.b32 %0, 1, 0, p;\n}"
                 : "=r"(done) : "r"(bar), "r"(ph) : "memory");
    while (!done) {
        asm volatile("{\n .reg .pred p;\n"
                     " mbarrier.try_wait.parity.acquire.cta.shared::cta.b64 p, [%1], %2, 0x989680;\n"
                     " selp.b32 %0, 1, 0, p;\n}"
                     : "=r"(done) : "r"(bar), "r"(ph) : "memory");
    }
}

__device__ __forceinline__ void issue_tma(const char* gsrc, float* sE, int kn,
                                          unsigned long long* mbar) {
    unsigned bar = smem_u32(&mbar[kn & (NST - 1)]);
    asm volatile("mbarrier.arrive.expect_tx.shared::cta.b64 _, [%0], %1;"
                 :: "r"(bar), "r"((unsigned)STAGE_BYTES));
    asm volatile("cp.async.bulk.shared::cta.global.mbarrier::complete_tx::bytes "
                 "[%0], [%1], %2, [%3];"
                 :: "r"(smem_u32(sE) + (kn & (NST - 1)) * STAGE_BYTES),
                    "l"(gsrc + (size_t)kn * STAGE_BYTES),
                    "r"((unsigned)STAGE_BYTES), "r"(bar) : "memory");
}

// ---------------------------------------------------------------------------
// prep: pack variant -> [j4][m] words; zero vlog (atomicAdd target)
// ---------------------------------------------------------------------------
__global__ void prep_kernel(const int* __restrict__ variant,
                            float* __restrict__ vlog) {
    int tid = blockIdx.x * blockDim.x + threadIdx.x;    // 8192 = 128m x 64 j4
    int m  = tid >> 6;
    int j4 = tid & 63;
    int4 v = ((const int4*)variant)[m * 64 + j4];       // coalesced
    unsigned w = (unsigned)v.x | ((unsigned)v.y << 8) |
                 ((unsigned)v.z << 16) | ((unsigned)v.w << 24);
    g_dselp[j4 * Mv + m] = w;
    if (tid < Mv) vlog[tid] = 0.0f;
}

// ---------------------------------------------------------------------------
// fused: 256 CTAs x 256 threads. 4-stage x 15.5KB pipeline, CTA-wide sync
// only every 2 chunks (16 syncs total, as r10), fine-grained mbarrier waits.
// No inter-CTA dependency anywhere -> correct at ANY residency.
// ---------------------------------------------------------------------------
__global__ __launch_bounds__(256, 2) void fused_kernel(
    const int*   __restrict__ variant,
    const float* __restrict__ vmask,
    const float* __restrict__ eij,
    const float* __restrict__ ei,
    const float* __restrict__ mask_vec,
    const float* __restrict__ sigma,
    float* __restrict__ motifs,      // [Mv,Nv,Cv]
    float* __restrict__ logits,      // [Mv,Nv]
    float* __restrict__ vlog)        // [Mv]
{
    extern __shared__ __align__(128) float sE[];        // [NST][STAGE_FLOATS]
    __shared__ __align__(8) unsigned long long mbar[NST];
    __shared__ float smask[32];
    __shared__ float sei[Cv];
    __shared__ float slog[Mv];

    const int i  = blockIdx.x;
    const int t  = threadIdx.x;
    const int m  = t & (Mv - 1);
    const int c0 = (t >> 7) * CHALF;

    if (t < Cv) { smask[t] = mask_vec[t]; sei[t] = ei[i * Cv + t]; }
    if (t == 0) {
        #pragma unroll
        for (int s = 0; s < NST; ++s)
            asm volatile("mbarrier.init.shared.b64 [%0], 1;"
                         :: "r"(smem_u32(&mbar[s])));
    }
    __syncthreads();

    const char* gsrc = (const char*)(eij + (size_t)i * (Nv * TILE));

    // prime 3 of 4 stages: compute can start after the FIRST 15.5KB lands
    if (t == 0) {
        issue_tma(gsrc, sE, 0, mbar);
        issue_tma(gsrc, sE, 1, mbar);
        issue_tma(gsrc, sE, 2, mbar);
    }

    float acc[CHALF];
    #pragma unroll
    for (int cc = 0; cc < CHALF; ++cc) acc[cc] = 0.0f;

    for (int k = 0; k < NCHUNK; ++k) {
        const int s = k & (NST - 1);
        const unsigned ph = (unsigned)(k >> 2) & 1u;

        // 2 coalesced words = 8 class ids, loaded before the wait
        unsigned w0 = g_dselp[(k * 2 + 0) * Mv + m];
        unsigned w1 = g_dselp[(k * 2 + 1) * Mv + m];

        wait_parity(smem_u32(&mbar[s]), ph);

        int d8[8];
        #pragma unroll
        for (int b = 0; b < 4; ++b) {
            d8[b]     = (w0 >> (8 * b)) & 0xFF;
            d8[4 + b] = (w1 >> (8 * b)) & 0xFF;
        }
        float s8[8];
        #pragma unroll
        for (int jj = 0; jj < 8; ++jj) s8[jj] = smask[d8[jj]];

        const float* buf = sE + s * STAGE_FLOATS;
        #pragma unroll
        for (int jl = 0; jl < 8; ++jl) {
            const float* row = buf + jl * TILE + c0 * Cv + d8[jl];
            const float sc = s8[jl];
            #pragma unroll
            for (int cc = 0; cc < CHALF; ++cc)
                acc[cc] = fmaf(sc, row[cc * Cv], acc[cc]);   // conflict-free LDS
        }

        // CTA-wide sync only every 2 chunks; then refill two stages.
        // Guard: TMA(k+2)/(k+3) overwrite stages consumed at chunks k-2/k-1,
        // both covered by this barrier.
        if (k & 1) {
            __syncthreads();
            if (t == 0) {
                if (k + 2 < NCHUNK) issue_tma(gsrc, sE, k + 2, mbar);
                if (k + 3 < NCHUNK) issue_tma(gsrc, sE, k + 3, mbar);
            }
        }
    }

    // ---- epilogue: motifs, logits, atomic pooled delta (proven) ----
    const int vmi = variant[m * Nv + i];
    float* mout = motifs + ((size_t)m * Nv + i) * Cv;
    float myl = 0.0f;
    const bool own = (vmi >= c0) && (vmi < c0 + CHALF);
    #pragma unroll
    for (int cc = 0; cc < CHALF; ++cc) {
        const int c = c0 + cc;
        const float v = acc[cc] + sei[c];
        mout[c] = v;
        if (c == vmi) myl = v;
    }
    if (own) slog[m] = myl;
    __syncthreads();

    if (t < Mv) {
        const float lm = slog[t];
        logits[t * Nv + i] = lm;
        const float w = vmask[t * Nv + i] * vmask[i];
        atomicAdd(&vlog[t], (lm - slog[0]) * w * sigma[0]);
    }
}

// ---------------------------------------------------------------------------
// Load-time attribute opt-in (NEVER inside kernel_launch / graph capture).
// ---------------------------------------------------------------------------
static struct _AttrInit {
    _AttrInit() {
        cudaFuncSetAttribute(fused_kernel,
                             cudaFuncAttributeMaxDynamicSharedMemorySize, DSMEM);
    }
} _attr_init;

// ---------------------------------------------------------------------------
extern "C" void kernel_launch(void* const* d_in, const int* in_sizes, int n_in,
                              void* d_out, int out_size) {
    int idx_eij = 2, idx_ei = 3, idx_mask = 4, idx_sigma = 5;
    int big1 = 0, big2 = 1;
    {
        int b1 = -1, b2 = -1;
        for (int q = 0; q < n_in; ++q) {
            int s = in_sizes[q];
            if (s == Nv * Nv * Cv * Cv)      idx_eij = q;
            else if (s == Nv * Cv)           idx_ei = q;
            else if (s == Cv)                idx_mask = q;
            else if (s == 1)                 idx_sigma = q;
            else if (s == Mv * Nv) { if (b1 < 0) b1 = q; else b2 = q; }
        }
        if (b1 >= 0) big1 = b1;
        if (b2 >= 0) big2 = b2;
    }

    const int*   variant = (const int*)d_in[big1];
    const float* vmask   = (const float*)d_in[big2];
    const float* eij     = (const float*)d_in[idx_eij];
    const float* ei      = (const float*)d_in[idx_ei];
    const float* maskv   = (const float*)d_in[idx_mask];
    const float* sigma   = (const float*)d_in[idx_sigma];

    float* out    = (float*)d_out;
    float* motifs = out;                               // [128,256,22]
    float* logits = out + (size_t)Mv * Nv * Cv;        // [128,256]
    float* vlog   = logits + (size_t)Mv * Nv;          // [128,1]

    prep_kernel<<<32, 256>>>(variant, vlog);
    fused_kernel<<<NB, 256, DSMEM>>>(variant, vmask, eij, ei, maskv, sigma,
                                     motifs, logits, vlog);
}

// round 17
// speedup vs baseline: 1.0979x; 1.0486x over previous
#include <cuda_runtime.h>
#include <stdint.h>

#define Mv 128
#define Nv 256
#define Cv 22
#define TILE (Cv*Cv)                  // 484 floats per (i,j) tile
#define JC 16                         // j per chunk
#define NCHUNK (Nv/JC)                // 16 chunks
#define NST 2                         // double buffer
#define STAGE_FLOATS (JC*TILE)        // 7744 floats
#define STAGE_BYTES  (STAGE_FLOATS*4) // 30976 B
#define DSMEM (NST*STAGE_BYTES)       // 61952 B dynamic
#define CHALF 11
#define NB 256

__device__ unsigned g_dselp[(Nv/4) * Mv];   // [j4][m], 4 packed classes/word
__device__ float4   g_smask4[(Nv/4) * Mv];  // [j4][m], 4 masked weights/float4

__device__ __forceinline__ unsigned smem_u32(const void* p) {
    return (unsigned)__cvta_generic_to_shared(p);
}

__device__ __forceinline__ void wait_parity(unsigned bar, unsigned ph) {
    unsigned done;
    asm volatile("{\n .reg .pred p;\n"
                 " mbarrier.try_wait.parity.acquire.cta.shared::cta.b64 p, [%1], %2;\n"
                 " selp.b32 %0, 1, 0, p;\n}"
                 : "=r"(done) : "r"(bar), "r"(ph) : "memory");
    while (!done) {
        asm volatile("{\n .reg .pred p;\n"
                     " mbarrier.try_wait.parity.acquire.cta.shared::cta.b64 p, [%1], %2, 0x989680;\n"
                     " selp.b32 %0, 1, 0, p;\n}"
                     : "=r"(done) : "r"(bar), "r"(ph) : "memory");
    }
}

// ---------------------------------------------------------------------------
// prep: pack classes AND masked weights into [j4][m] tables; zero vlog
// ---------------------------------------------------------------------------
__global__ void prep_kernel(const int* __restrict__ variant,
                            const float* __restrict__ mask_vec,
                            float* __restrict__ vlog) {
    int tid = blockIdx.x * blockDim.x + threadIdx.x;    // 8192 = 128m x 64 j4
    int m  = tid >> 6;
    int j4 = tid & 63;
    int4 v = ((const int4*)variant)[m * 64 + j4];       // coalesced
    unsigned w = (unsigned)v.x | ((unsigned)v.y << 8) |
                 ((unsigned)v.z << 16) | ((unsigned)v.w << 24);
    g_dselp[j4 * Mv + m] = w;
    float4 s4;
    s4.x = mask_vec[v.x]; s4.y = mask_vec[v.y];
    s4.z = mask_vec[v.z]; s4.w = mask_vec[v.w];
    g_smask4[j4 * Mv + m] = s4;
    if (tid < Mv) vlog[tid] = 0.0f;
}

// ---------------------------------------------------------------------------
// fused: 256 CTAs x 256 threads, JC=16 double-buffered TMA pipeline.
// No inter-CTA dependency anywhere -> correct at ANY residency (no deadlock).
// ---------------------------------------------------------------------------
__global__ __launch_bounds__(256, 2) void fused_kernel(
    const int*   __restrict__ variant,
    const float* __restrict__ vmask,
    const float* __restrict__ eij,
    const float* __restrict__ ei,
    const float* __restrict__ sigma,
    float* __restrict__ motifs,      // [Mv,Nv,Cv]
    float* __restrict__ logits,      // [Mv,Nv]
    float* __restrict__ vlog)        // [Mv]
{
    extern __shared__ __align__(128) float sE[];        // [NST][STAGE_FLOATS]
    __shared__ __align__(8) unsigned long long mbar[NST];
    __shared__ float sei[Cv];
    __shared__ float slog[Mv];

    const int i  = blockIdx.x;
    const int t  = threadIdx.x;
    const int m  = t & (Mv - 1);
    const int c0 = (t >> 7) * CHALF;

    if (t < Cv) sei[t] = ei[i * Cv + t];
    if (t == 0) {
        #pragma unroll
        for (int s = 0; s < NST; ++s)
            asm volatile("mbarrier.init.shared.b64 [%0], 1;"
                         :: "r"(smem_u32(&mbar[s])));
    }
    __syncthreads();

    const char* gsrc = (const char*)(eij + (size_t)i * (Nv * TILE));

    // prime both stages
    if (t == 0) {
        #pragma unroll
        for (int k = 0; k < 2; ++k) {
            unsigned bar = smem_u32(&mbar[k]);
            asm volatile("mbarrier.arrive.expect_tx.shared::cta.b64 _, [%0], %1;"
                         :: "r"(bar), "r"((unsigned)STAGE_BYTES));
            asm volatile("cp.async.bulk.shared::cta.global.mbarrier::complete_tx::bytes "
                         "[%0], [%1], %2, [%3];"
                         :: "r"(smem_u32(sE) + k * STAGE_BYTES),
                            "l"(gsrc + (size_t)k * STAGE_BYTES),
                            "r"((unsigned)STAGE_BYTES), "r"(bar) : "memory");
        }
    }

    float acc[CHALF];
    #pragma unroll
    for (int cc = 0; cc < CHALF; ++cc) acc[cc] = 0.0f;

    for (int k = 0; k < NCHUNK; ++k) {
        const int s = k & 1;
        const unsigned ph = (unsigned)(k >> 1) & 1u;

        // class ids + masked weights for 16 j: all coalesced, issued pre-wait
        unsigned w4[4];
        float4   sv[4];
        #pragma unroll
        for (int q = 0; q < 4; ++q) {
            w4[q] = g_dselp[(k * 4 + q) * Mv + m];
            sv[q] = g_smask4[(k * 4 + q) * Mv + m];
        }

        wait_parity(smem_u32(&mbar[s]), ph);

        const float* buf = sE + s * STAGE_FLOATS;
        #pragma unroll
        for (int half = 0; half < 2; ++half) {          // 8 j per half-pass
            const unsigned wa = w4[half * 2], wb = w4[half * 2 + 1];
            int d8[8];
            #pragma unroll
            for (int b = 0; b < 4; ++b) {
                d8[b]     = (wa >> (8 * b)) & 0xFF;
                d8[4 + b] = (wb >> (8 * b)) & 0xFF;
            }
            float s8[8];
            s8[0] = sv[half * 2].x;     s8[1] = sv[half * 2].y;
            s8[2] = sv[half * 2].z;     s8[3] = sv[half * 2].w;
            s8[4] = sv[half * 2 + 1].x; s8[5] = sv[half * 2 + 1].y;
            s8[6] = sv[half * 2 + 1].z; s8[7] = sv[half * 2 + 1].w;

            #pragma unroll
            for (int jl = 0; jl < 8; ++jl) {
                const float* row = buf + (half * 8 + jl) * TILE + c0 * Cv + d8[jl];
                const float sc = s8[jl];
                #pragma unroll
                for (int cc = 0; cc < CHALF; ++cc)
                    acc[cc] = fmaf(sc, row[cc * Cv], acc[cc]);  // conflict-free LDS
            }
        }

        __syncthreads();   // all done with chunk k -> stage s reusable
        if (t == 0 && k + 2 < NCHUNK) {
            const int kn = k + 2;                       // same stage s, next phase
            unsigned bar = smem_u32(&mbar[s]);
            asm volatile("mbarrier.arrive.expect_tx.shared::cta.b64 _, [%0], %1;"
                         :: "r"(bar), "r"((unsigned)STAGE_BYTES));
            asm volatile("cp.async.bulk.shared::cta.global.mbarrier::complete_tx::bytes "
                         "[%0], [%1], %2, [%3];"
                         :: "r"(smem_u32(sE) + s * STAGE_BYTES),
                            "l"(gsrc + (size_t)kn * STAGE_BYTES),
                            "r"((unsigned)STAGE_BYTES), "r"(bar) : "memory");
        }
    }

    // ---- epilogue: motifs (float2 stores), logits, atomic pooled delta ----
    const int vmi = variant[m * Nv + i];
    float* mout = motifs + ((size_t)m * Nv + i) * Cv;
    float vv[CHALF];
    float myl = 0.0f;
    const bool own = (vmi >= c0) && (vmi < c0 + CHALF);
    #pragma unroll
    for (int cc = 0; cc < CHALF; ++cc) {
        const int c = c0 + cc;
        vv[cc] = acc[cc] + sei[c];
        if (c == vmi) myl = vv[cc];
    }
    // 88-byte (m,i) rows are 8B-aligned at offsets 0 and 48 -> float2 legal
    if (c0 == 0) {
        #pragma unroll
        for (int p = 0; p < 5; ++p)
            *(float2*)(mout + 2 * p) = make_float2(vv[2 * p], vv[2 * p + 1]);
        mout[10] = vv[10];
    } else {
        mout[11] = vv[0];
        #pragma unroll
        for (int p = 0; p < 5; ++p)
            *(float2*)(mout + 12 + 2 * p) = make_float2(vv[1 + 2 * p], vv[2 + 2 * p]);
    }
    if (own) slog[m] = myl;
    __syncthreads();

    if (t < Mv) {
        const float lm = slog[t];
        logits[t * Nv + i] = lm;
        const float w = vmask[t * Nv + i] * vmask[i];
        atomicAdd(&vlog[t], (lm - slog[0]) * w * sigma[0]);
    }
}

// ---------------------------------------------------------------------------
// Load-time attribute opt-in (NEVER inside kernel_launch / graph capture).
// ---------------------------------------------------------------------------
static struct _AttrInit {
    _AttrInit() {
        cudaFuncSetAttribute(fused_kernel,
                             cudaFuncAttributeMaxDynamicSharedMemorySize, DSMEM);
    }
} _attr_init;

// ---------------------------------------------------------------------------
extern "C" void kernel_launch(void* const* d_in, const int* in_sizes, int n_in,
                              void* d_out, int out_size) {
    int idx_eij = 2, idx_ei = 3, idx_mask = 4, idx_sigma = 5;
    int big1 = 0, big2 = 1;
    {
        int b1 = -1, b2 = -1;
        for (int q = 0; q < n_in; ++q) {
            int s = in_sizes[q];
            if (s == Nv * Nv * Cv * Cv)      idx_eij = q;
            else if (s == Nv * Cv)           idx_ei = q;
            else if (s == Cv)                idx_mask = q;
            else if (s == 1)                 idx_sigma = q;
            else if (s == Mv * Nv) { if (b1 < 0) b1 = q; else b2 = q; }
        }
        if (b1 >= 0) big1 = b1;
        if (b2 >= 0) big2 = b2;
    }

    const int*   variant = (const int*)d_in[big1];
    const float* vmask   = (const float*)d_in[big2];
    const float* eij     = (const float*)d_in[idx_eij];
    const float* ei      = (const float*)d_in[idx_ei];
    const float* maskv   = (const float*)d_in[idx_mask];
    const float* sigma   = (const float*)d_in[idx_sigma];

    float* out    = (float*)d_out;
    float* motifs = out;                               // [128,256,22]
    float* logits = out + (size_t)Mv * Nv * Cv;        // [128,256]
    float* vlog   = logits + (size_t)Mv * Nv;          // [128,1]

    prep_kernel<<<32, 256>>>(variant, maskv, vlog);
    fused_kernel<<<NB, 256, DSMEM>>>(variant, vmask, eij, ei, sigma,
                                     motifs, logits, vlog);
}